// round 14
// baseline (speedup 1.0000x reference)
#include <cuda_runtime.h>
#include <cuda_bf16.h>
#include <math.h>
#include <stdint.h>

#define NN 50000
#define EE 800000

typedef __nv_bfloat16 bf16;
typedef __nv_bfloat162 bf162;

// ---------------- device scratch (no allocation allowed) ----------------
__device__ __align__(256) bf16  g_p [NN * 256];
__device__ __align__(256) bf16  g_sA[NN * 256];
__device__ __align__(256) bf16  g_sB[NN * 256];
__device__ __align__(256) bf16  g_h [NN * 256];
__device__ __align__(256) bf16  g_u [NN * 512];
__device__ __align__(256) bf16  g_xb[NN * 128];
__device__ __align__(256) unsigned g_wpack[262144];
__device__ float g_dinv[NN];
__device__ int   g_deg[NN];
__device__ int   g_rowptr[NN + 1];
__device__ int   g_cur[NN];
__device__ int   g_tmp[NN];
__device__ int   g_bsum[64];
__device__ int   g_csrs[EE];
__device__ float g_csrw[EE];

__device__ __forceinline__ float gelu_f(float x) {
    return 0.5f * x * (1.0f + erff(x * 0.7071067811865476f));
}

// ---------------- weight pack / x convert ----------------
struct PackSeg { const float* src; unsigned* dst; int ncols; int mode; unsigned count; };
struct PackArgs { PackSeg seg[10]; unsigned total; };

__global__ void pack_kernel(PackArgs pa) {
    unsigned u = blockIdx.x * 256 + threadIdx.x;
    if (u >= pa.total) return;
    int s = 0; unsigned base = 0;
    while (u >= base + pa.seg[s].count) { base += pa.seg[s].count; s++; }
    unsigned i = u - base;
    const float* src = pa.seg[s].src;
    float lo, hi;
    if (pa.seg[s].mode == 0) {
        int N = pa.seg[s].ncols;
        unsigned kp = i / N, n = i % N;
        lo = src[(size_t)(2 * kp) * N + n];
        hi = src[(size_t)(2 * kp + 1) * N + n];
    } else {
        lo = src[2 * (size_t)i];
        hi = src[2 * (size_t)i + 1];
    }
    bf162 h2 = __float22bfloat162_rn(make_float2(lo, hi));
    pa.seg[s].dst[i] = *(unsigned*)&h2;
}

// ---------------- degree ----------------
__global__ void deg_kernel(const int* __restrict__ dst, int* __restrict__ deg, int E) {
    int e = blockIdx.x * blockDim.x + threadIdx.x;
    if (e < E) atomicAdd(&deg[dst[e]], 1);
}

// ---------------- 3-kernel exclusive scan of deg -> rowptr (+dinv) --------
__global__ void scan_blk(const int* __restrict__ deg, int* __restrict__ tmp,
                         int* __restrict__ bsum, int n) {
    __shared__ int s[1024];
    int i = blockIdx.x * 1024 + threadIdx.x;
    int v = (i < n) ? deg[i] : 0;
    s[threadIdx.x] = v;
    __syncthreads();
#pragma unroll
    for (int o = 1; o < 1024; o <<= 1) {
        int t = (threadIdx.x >= o) ? s[threadIdx.x - o] : 0;
        __syncthreads();
        s[threadIdx.x] += t;
        __syncthreads();
    }
    if (i < n) tmp[i] = s[threadIdx.x];
    if (threadIdx.x == 1023) bsum[blockIdx.x] = s[1023];
}

__global__ void scan_top(int* __restrict__ bsum, int nb) {
    __shared__ int s[64];
    int v = (threadIdx.x < nb) ? bsum[threadIdx.x] : 0;
    s[threadIdx.x] = v;
    __syncthreads();
#pragma unroll
    for (int o = 1; o < 64; o <<= 1) {
        int t = (threadIdx.x >= o) ? s[threadIdx.x - o] : 0;
        __syncthreads();
        s[threadIdx.x] += t;
        __syncthreads();
    }
    if (threadIdx.x < nb) bsum[threadIdx.x] = s[threadIdx.x];
}

__global__ void scan_add(const int* __restrict__ tmp, const int* __restrict__ bsum,
                         const int* __restrict__ deg, float* __restrict__ dinv,
                         int* __restrict__ rowptr, int* __restrict__ cur, int n) {
    int i = blockIdx.x * blockDim.x + threadIdx.x;
    if (i > n) return;
    int v;
    if (i == 0) v = 0;
    else {
        int j = i - 1;
        v = tmp[j] + ((j >= 1024) ? bsum[j / 1024 - 1] : 0);
    }
    rowptr[i] = v;
    if (i < n) {
        cur[i] = v;
        dinv[i] = rsqrtf((float)deg[i] + 1.0f);
    }
}

// ---------------- CSR bucket fill (also computes edge weights) ----------------
__global__ void fill_kernel(const int* __restrict__ src, const int* __restrict__ dst,
                            const float* __restrict__ dinv, int* __restrict__ cur,
                            int* __restrict__ csrs, float* __restrict__ csrw, int E) {
    int e = blockIdx.x * blockDim.x + threadIdx.x;
    if (e >= E) return;
    int s = src[e], d = dst[e];
    int pos = atomicAdd(&cur[d], 1);
    csrs[pos] = s;
    csrw[pos] = dinv[s] * dinv[d];
}

// ------- CSR gather, warp per row (bf16 in/out, fp32 accumulate) ------------
template<int D>
__global__ __launch_bounds__(256)
void gather_warp(const bf16* __restrict__ h, const float* __restrict__ dinv,
                 const int* __restrict__ rowptr, const int* __restrict__ csrs,
                 const float* __restrict__ csrw, bf16* __restrict__ p) {
    constexpr int VEC = D / 32;     // bf16 per lane
    constexpr int N2  = VEC / 2;    // bf162 per lane
    const int wid  = threadIdx.x >> 5;
    const int lane = threadIdx.x & 31;
    const int row  = blockIdx.x * 8 + wid;
    if (row >= NN) return;

    const int start = rowptr[row];
    const int end   = rowptr[row + 1];
    const bf16* selfp = h + (size_t)row * D + lane * VEC;

    float acc[VEC];
    {
        float w = dinv[row]; w = w * w;
        uint4 q;
        if (VEC == 8) q = *(const uint4*)selfp;
        else { uint2 t = *(const uint2*)selfp; q.x = t.x; q.y = t.y; q.z = 0; q.w = 0; }
        const bf162* b2 = (const bf162*)&q;
#pragma unroll
        for (int c = 0; c < N2; c++) {
            float2 f = __bfloat1622float2(b2[c]);
            acc[2 * c]     = w * f.x;
            acc[2 * c + 1] = w * f.y;
        }
    }

    int j = start;
    for (; j + 1 < end; j += 2) {
        int   s0 = csrs[j],     s1 = csrs[j + 1];
        float w0 = csrw[j],     w1 = csrw[j + 1];
        const bf16* p0 = h + (size_t)s0 * D + lane * VEC;
        const bf16* p1 = h + (size_t)s1 * D + lane * VEC;
        uint4 q0, q1;
        if (VEC == 8) { q0 = *(const uint4*)p0; q1 = *(const uint4*)p1; }
        else {
            uint2 t0 = *(const uint2*)p0, t1 = *(const uint2*)p1;
            q0.x = t0.x; q0.y = t0.y; q1.x = t1.x; q1.y = t1.y;
            q0.z = q0.w = q1.z = q1.w = 0;
        }
        const bf162* a0 = (const bf162*)&q0;
        const bf162* a1 = (const bf162*)&q1;
#pragma unroll
        for (int c = 0; c < N2; c++) {
            float2 f0 = __bfloat1622float2(a0[c]);
            float2 f1 = __bfloat1622float2(a1[c]);
            acc[2 * c]     += w0 * f0.x + w1 * f1.x;
            acc[2 * c + 1] += w0 * f0.y + w1 * f1.y;
        }
    }
    if (j < end) {
        int   s0 = csrs[j];
        float w0 = csrw[j];
        const bf16* p0 = h + (size_t)s0 * D + lane * VEC;
        uint4 q0;
        if (VEC == 8) q0 = *(const uint4*)p0;
        else { uint2 t0 = *(const uint2*)p0; q0.x = t0.x; q0.y = t0.y; q0.z = q0.w = 0; }
        const bf162* a0 = (const bf162*)&q0;
#pragma unroll
        for (int c = 0; c < N2; c++) {
            float2 f0 = __bfloat1622float2(a0[c]);
            acc[2 * c]     += w0 * f0.x;
            acc[2 * c + 1] += w0 * f0.y;
        }
    }

    bf16* prow = p + (size_t)row * D + lane * VEC;
    uint4 o;
    bf162* ob = (bf162*)&o;
#pragma unroll
    for (int c = 0; c < N2; c++)
        ob[c] = __float22bfloat162_rn(make_float2(acc[2 * c], acc[2 * c + 1]));
    if (VEC == 8) *(uint4*)prow = o;
    else          *(uint2*)prow = make_uint2(o.x, o.y);
}

// ======== fused conv GEMM + LayerNorm + GELU ===============================
// snew = p@Wc + skip@Wp + bc + bp   (written bf16 iff EMITS)
// h    = gelu(LN(snew; gn, be))     (always written)
// BM=128, BN=256 (full row), 512 threads (16 warps 4m x 4n), 3-stage pipeline.
template<bool EMITS>
__global__ __launch_bounds__(512)
void conv_gemm_ln(const bf16* __restrict__ A1, const unsigned* __restrict__ W1, int K1,
                  const bf16* __restrict__ A2, const unsigned* __restrict__ W2, int K2,
                  const float* __restrict__ b1, const float* __restrict__ b2,
                  const float* __restrict__ gnv, const float* __restrict__ bev,
                  bf16* __restrict__ outS, bf16* __restrict__ outH, int M) {
    constexpr int ASTR = 20;
    constexpr int BSTR = 264;              // 256+8, ≡8 mod 32
    constexpr int AU = 128 * ASTR;         // 2560 u32
    constexpr int BU = 16 * BSTR;          // 4224 u32
    constexpr int BUFF = AU + BU;          // 6784 u32

    extern __shared__ __align__(16) unsigned smem[];

    const int tid  = threadIdx.x;
    const int lane = tid & 31;
    const int warp = tid >> 5;             // 0..15
    const int wm   = warp >> 2;            // 0..3 -> 32-row slab
    const int wn   = warp & 3;             // 0..3 -> 64-col slab
    const int gid  = lane >> 2;
    const int tig  = lane & 3;
    const int rowBase = blockIdx.y * 128;

    const uint32_t sbase = (uint32_t)__cvta_generic_to_shared(smem);

    float acc[2][8][4];
#pragma unroll
    for (int mt = 0; mt < 2; mt++)
#pragma unroll
        for (int nt = 0; nt < 8; nt++)
#pragma unroll
            for (int i = 0; i < 4; i++) acc[mt][nt][i] = 0.0f;

    const int nT1 = K1 / 32;
    const int nT  = nT1 + K2 / 32;

    auto cpTile = [&](int t, int stg) {
        const bf16* A; const unsigned* W; int K, k0;
        if (t < nT1) { A = A1; W = W1; K = K1; k0 = t * 32; }
        else         { A = A2; W = W2; K = K2; k0 = (t - nT1) * 32; }
        const uint32_t aoff = sbase + (uint32_t)(stg * BUFF) * 4u;
        const uint32_t boff = aoff + (uint32_t)AU * 4u;
        // A: 128 rows x 16 u32 = 512 chunks, one per thread
        {
            int r  = tid >> 2;
            int c4 = (tid & 3) << 2;
            int grow = rowBase + r;
            int sz = (grow < M) ? 16 : 0;
            const bf16* g = A + (size_t)((grow < M) ? grow : 0) * K + k0 + 2 * c4;
            uint32_t sa = aoff + (uint32_t)(r * ASTR + c4) * 4u;
            asm volatile("cp.async.ca.shared.global [%0], [%1], 16, %2;\n"
                         :: "r"(sa), "l"(g), "r"(sz));
        }
        // B: 16 kp-rows x 256 u32 = 1024 chunks, two per thread
#pragma unroll
        for (int i = 0; i < 2; i++) {
            int idx = tid + i * 512;
            int r   = idx >> 6;
            int c4  = (idx & 63) << 2;
            const unsigned* g = W + (size_t)(k0 / 2 + r) * 256 + c4;
            uint32_t sa = boff + (uint32_t)(r * BSTR + c4) * 4u;
            asm volatile("cp.async.ca.shared.global [%0], [%1], 16, %2;\n"
                         :: "r"(sa), "l"(g), "r"(16));
        }
        asm volatile("cp.async.commit_group;\n" ::);
    };

    cpTile(0, 0);
    if (nT > 1) cpTile(1, 1);

    int stg = 0;
    for (int t = 0; t < nT; t++) {
        if (t + 1 < nT) asm volatile("cp.async.wait_group 1;\n" ::);
        else            asm volatile("cp.async.wait_group 0;\n" ::);
        __syncthreads();
        if (t + 2 < nT) {
            int ns = stg + 2; if (ns >= 3) ns -= 3;
            cpTile(t + 2, ns);
        }

        const unsigned* As = smem + stg * BUFF;
        const unsigned* Bs = As + AU;
#pragma unroll
        for (int ks = 0; ks < 2; ks++) {
            const int kb = ks * 8;
            unsigned a[2][4];
            unsigned b[8][2];
#pragma unroll
            for (int mt = 0; mt < 2; mt++) {
                int m = wm * 32 + mt * 16 + gid;
                a[mt][0] = As[m * ASTR + kb + tig];
                a[mt][1] = As[(m + 8) * ASTR + kb + tig];
                a[mt][2] = As[m * ASTR + kb + tig + 4];
                a[mt][3] = As[(m + 8) * ASTR + kb + tig + 4];
            }
#pragma unroll
            for (int nt = 0; nt < 8; nt++) {
                int n = wn * 64 + nt * 8 + gid;
                b[nt][0] = Bs[(kb + tig) * BSTR + n];
                b[nt][1] = Bs[(kb + tig + 4) * BSTR + n];
            }
#pragma unroll
            for (int mt = 0; mt < 2; mt++)
#pragma unroll
                for (int nt = 0; nt < 8; nt++) {
                    asm volatile(
                        "mma.sync.aligned.m16n8k16.row.col.f32.bf16.bf16.f32 "
                        "{%0,%1,%2,%3}, {%4,%5,%6,%7}, {%8,%9}, {%0,%1,%2,%3};\n"
                        : "+f"(acc[mt][nt][0]), "+f"(acc[mt][nt][1]),
                          "+f"(acc[mt][nt][2]), "+f"(acc[mt][nt][3])
                        : "r"(a[mt][0]), "r"(a[mt][1]), "r"(a[mt][2]), "r"(a[mt][3]),
                          "r"(b[nt][0]), "r"(b[nt][1]));
                }
        }
        stg++; if (stg >= 3) stg = 0;
    }

    // ---- epilogue: bias -> LN stats -> gelu, write snew + h ----
    // add bias into acc
#pragma unroll
    for (int nt = 0; nt < 8; nt++) {
        int cn = wn * 64 + nt * 8 + tig * 2;
        float bias0 = b1[cn] + b2[cn];
        float bias1 = b1[cn + 1] + b2[cn + 1];
#pragma unroll
        for (int mt = 0; mt < 2; mt++) {
            acc[mt][nt][0] += bias0; acc[mt][nt][1] += bias1;
            acc[mt][nt][2] += bias0; acc[mt][nt][3] += bias1;
        }
    }

    __syncthreads();   // mainloop smem reads done before aliasing
    float* sSum   = (float*)smem;            // [128][4]
    float* sSq    = sSum + 512;              // [128][4]
    float2* sStat = (float2*)(sSq + 512);    // [128]

    // per-thread partial sums over 16 cols, 4 rows
#pragma unroll
    for (int mt = 0; mt < 2; mt++)
#pragma unroll
        for (int half = 0; half < 2; half++) {
            float s = 0.f, q = 0.f;
#pragma unroll
            for (int nt = 0; nt < 8; nt++) {
                float v0 = acc[mt][nt][half * 2 + 0];
                float v1 = acc[mt][nt][half * 2 + 1];
                s += v0 + v1;
                q += v0 * v0 + v1 * v1;
            }
            s += __shfl_xor_sync(0xffffffffu, s, 1);
            q += __shfl_xor_sync(0xffffffffu, q, 1);
            s += __shfl_xor_sync(0xffffffffu, s, 2);
            q += __shfl_xor_sync(0xffffffffu, q, 2);
            if (tig == 0) {
                int rl = wm * 32 + mt * 16 + half * 8 + gid;
                sSum[rl * 4 + wn] = s;
                sSq [rl * 4 + wn] = q;
            }
        }
    __syncthreads();
    if (tid < 128) {
        float s = sSum[tid * 4] + sSum[tid * 4 + 1] + sSum[tid * 4 + 2] + sSum[tid * 4 + 3];
        float q = sSq [tid * 4] + sSq [tid * 4 + 1] + sSq [tid * 4 + 2] + sSq [tid * 4 + 3];
        float mean = s * (1.0f / 256.0f);
        float var  = q * (1.0f / 256.0f) - mean * mean;
        sStat[tid] = make_float2(mean, rsqrtf(var + 1e-5f));
    }
    __syncthreads();

#pragma unroll
    for (int mt = 0; mt < 2; mt++)
#pragma unroll
        for (int half = 0; half < 2; half++) {
            int rl = wm * 32 + mt * 16 + half * 8 + gid;
            int row = rowBase + rl;
            if (row >= M) continue;
            float2 st = sStat[rl];
#pragma unroll
            for (int nt = 0; nt < 8; nt++) {
                int cn = wn * 64 + nt * 8 + tig * 2;
                float v0 = acc[mt][nt][half * 2 + 0];
                float v1 = acc[mt][nt][half * 2 + 1];
                if (EMITS) {
                    bf162 o = __float22bfloat162_rn(make_float2(v0, v1));
                    *(unsigned*)(outS + (size_t)row * 256 + cn) = *(unsigned*)&o;
                }
                float g0 = gnv[cn], g1 = gnv[cn + 1];
                float e0 = bev[cn], e1 = bev[cn + 1];
                float h0 = gelu_f((v0 - st.x) * st.y * g0 + e0);
                float h1 = gelu_f((v1 - st.x) * st.y * g1 + e1);
                bf162 oh = __float22bfloat162_rn(make_float2(h0, h1));
                *(unsigned*)(outH + (size_t)row * 256 + cn) = *(unsigned*)&oh;
            }
        }
}

// ---------------- bf16 tensor-core GEMM (m16n8k16) ----------------
// out = act( A1@W1 [+ addM] + b1 ). 3-stage pipeline, 2 CTAs/SM.
// LSM: stage logits in smem, fused log_softmax (BN==64 only), out fp32.
template<int BN, int ACT, bool ADDM, bool OUTBF, bool LSM>
__global__ __launch_bounds__(256, 2)
void bf16_gemm(const bf16* __restrict__ A1, const unsigned* __restrict__ W1, int K1,
               const float* __restrict__ b1,
               const bf16* __restrict__ addM, void* __restrict__ outv,
               int M, int NC) {
    constexpr int BM = 128;
    constexpr int ASTR = 20;
    constexpr int BSTR = BN + 8;
    constexpr int AU  = BM * ASTR;
    constexpr int BU  = 16 * BSTR;
    constexpr int BUFF = AU + BU;
    constexpr int NT  = BN / 16;

    extern __shared__ __align__(16) unsigned smem[];

    const int tid  = threadIdx.x;
    const int lane = tid & 31;
    const int warp = tid >> 5;
    const int wm   = warp & 3;
    const int wn   = warp >> 2;
    const int gid  = lane >> 2;
    const int tig  = lane & 3;
    const int rowBase = blockIdx.y * BM;
    const int colBase = blockIdx.x * BN;

    const uint32_t sbase = (uint32_t)__cvta_generic_to_shared(smem);

    float acc[2][NT][4];
#pragma unroll
    for (int mt = 0; mt < 2; mt++)
#pragma unroll
        for (int nt = 0; nt < NT; nt++)
#pragma unroll
            for (int i = 0; i < 4; i++) acc[mt][nt][i] = 0.0f;

    const int nT = K1 / 32;

    auto cpTile = [&](int t, int stg) {
        const int k0 = t * 32;
        const uint32_t aoff = sbase + (uint32_t)(stg * BUFF) * 4u;
        const uint32_t boff = aoff + (uint32_t)AU * 4u;
#pragma unroll
        for (int i = 0; i < 2; i++) {
            int idx = tid + i * 256;
            int r   = idx >> 2;
            int c4  = (idx & 3) << 2;
            int grow = rowBase + r;
            int sz = (grow < M) ? 16 : 0;
            const bf16* g = A1 + (size_t)((grow < M) ? grow : 0) * K1 + k0 + 2 * c4;
            uint32_t sa = aoff + (uint32_t)(r * ASTR + c4) * 4u;
            asm volatile("cp.async.ca.shared.global [%0], [%1], 16, %2;\n"
                         :: "r"(sa), "l"(g), "r"(sz));
        }
        constexpr int BI = (BN == 128) ? 2 : 1;
#pragma unroll
        for (int i = 0; i < BI; i++) {
            int idx = tid + i * 256;
            int r   = idx >> ((BN == 128) ? 5 : 4);
            int c4  = (idx & ((BN / 4) - 1)) << 2;
            const unsigned* g = W1 + (size_t)(k0 / 2 + r) * NC + colBase + c4;
            uint32_t sa = boff + (uint32_t)(r * BSTR + c4) * 4u;
            asm volatile("cp.async.ca.shared.global [%0], [%1], 16, %2;\n"
                         :: "r"(sa), "l"(g), "r"(16));
        }
        asm volatile("cp.async.commit_group;\n" ::);
    };

    cpTile(0, 0);
    if (nT > 1) cpTile(1, 1);

    int stg = 0;
    for (int t = 0; t < nT; t++) {
        if (t + 1 < nT) asm volatile("cp.async.wait_group 1;\n" ::);
        else            asm volatile("cp.async.wait_group 0;\n" ::);
        __syncthreads();
        if (t + 2 < nT) {
            int ns = stg + 2; if (ns >= 3) ns -= 3;
            cpTile(t + 2, ns);
        }

        const unsigned* As = smem + stg * BUFF;
        const unsigned* Bs = As + AU;
#pragma unroll
        for (int ks = 0; ks < 2; ks++) {
            const int kb = ks * 8;
            unsigned a[2][4];
            unsigned b[NT][2];
#pragma unroll
            for (int mt = 0; mt < 2; mt++) {
                int m = wm * 32 + mt * 16 + gid;
                a[mt][0] = As[m * ASTR + kb + tig];
                a[mt][1] = As[(m + 8) * ASTR + kb + tig];
                a[mt][2] = As[m * ASTR + kb + tig + 4];
                a[mt][3] = As[(m + 8) * ASTR + kb + tig + 4];
            }
#pragma unroll
            for (int nt = 0; nt < NT; nt++) {
                int n = wn * (BN / 2) + nt * 8 + gid;
                b[nt][0] = Bs[(kb + tig) * BSTR + n];
                b[nt][1] = Bs[(kb + tig + 4) * BSTR + n];
            }
#pragma unroll
            for (int mt = 0; mt < 2; mt++)
#pragma unroll
                for (int nt = 0; nt < NT; nt++) {
                    asm volatile(
                        "mma.sync.aligned.m16n8k16.row.col.f32.bf16.bf16.f32 "
                        "{%0,%1,%2,%3}, {%4,%5,%6,%7}, {%8,%9}, {%0,%1,%2,%3};\n"
                        : "+f"(acc[mt][nt][0]), "+f"(acc[mt][nt][1]),
                          "+f"(acc[mt][nt][2]), "+f"(acc[mt][nt][3])
                        : "r"(a[mt][0]), "r"(a[mt][1]), "r"(a[mt][2]), "r"(a[mt][3]),
                          "r"(b[nt][0]), "r"(b[nt][1]));
                }
        }
        stg++; if (stg >= 3) stg = 0;
    }

    if (LSM) {
        // stage logits (fp32) into smem, then fused log_softmax (BN==64)
        __syncthreads();
        float* lg = (float*)smem;    // [128][64] = 32KB
#pragma unroll
        for (int mt = 0; mt < 2; mt++) {
            int rl0 = wm * 32 + mt * 16 + gid;
#pragma unroll
            for (int nt = 0; nt < NT; nt++) {
                int cl = wn * (BN / 2) + nt * 8 + tig * 2;
                float bias0 = b1[cl], bias1 = b1[cl + 1];
                lg[rl0 * 64 + cl]           = acc[mt][nt][0] + bias0;
                lg[rl0 * 64 + cl + 1]       = acc[mt][nt][1] + bias1;
                lg[(rl0 + 8) * 64 + cl]     = acc[mt][nt][2] + bias0;
                lg[(rl0 + 8) * 64 + cl + 1] = acc[mt][nt][3] + bias1;
            }
        }
        __syncthreads();
        float* outp = (float*)outv;
        for (int r = warp * 16; r < warp * 16 + 16; r++) {
            int row = rowBase + r;
            if (row >= M) continue;
            float v0 = lg[r * 64 + lane * 2];
            float v1 = lg[r * 64 + lane * 2 + 1];
            float m = fmaxf(v0, v1);
#pragma unroll
            for (int o = 16; o; o >>= 1) m = fmaxf(m, __shfl_xor_sync(0xffffffffu, m, o));
            float s = expf(v0 - m) + expf(v1 - m);
#pragma unroll
            for (int o = 16; o; o >>= 1) s += __shfl_xor_sync(0xffffffffu, s, o);
            float l = m + logf(s);
            *(float2*)(outp + (size_t)row * 64 + lane * 2) = make_float2(v0 - l, v1 - l);
        }
        return;
    }

    // ---------------- standard epilogue ----------------
#pragma unroll
    for (int mt = 0; mt < 2; mt++) {
        const int r0 = rowBase + wm * 32 + mt * 16 + gid;
        const int r1 = r0 + 8;
#pragma unroll
        for (int nt = 0; nt < NT; nt++) {
            const int cn = colBase + wn * (BN / 2) + nt * 8 + tig * 2;
            float bias0 = b1[cn], bias1 = b1[cn + 1];
            float v0 = acc[mt][nt][0] + bias0;
            float v1 = acc[mt][nt][1] + bias1;
            float v2 = acc[mt][nt][2] + bias0;
            float v3 = acc[mt][nt][3] + bias1;
            if (r0 < M) {
                if (ADDM) {
                    unsigned q = *(const unsigned*)(addM + (size_t)r0 * NC + cn);
                    float2 f = __bfloat1622float2(*(const bf162*)&q);
                    v0 += f.x; v1 += f.y;
                }
                if (ACT == 1) { v0 = gelu_f(v0); v1 = gelu_f(v1); }
                if (OUTBF) {
                    bf162 o = __float22bfloat162_rn(make_float2(v0, v1));
                    *(unsigned*)((bf16*)outv + (size_t)r0 * NC + cn) = *(unsigned*)&o;
                } else {
                    *(float2*)((float*)outv + (size_t)r0 * NC + cn) = make_float2(v0, v1);
                }
            }
            if (r1 < M) {
                if (ADDM) {
                    unsigned q = *(const unsigned*)(addM + (size_t)r1 * NC + cn);
                    float2 f = __bfloat1622float2(*(const bf162*)&q);
                    v2 += f.x; v3 += f.y;
                }
                if (ACT == 1) { v2 = gelu_f(v2); v3 = gelu_f(v3); }
                if (OUTBF) {
                    bf162 o = __float22bfloat162_rn(make_float2(v2, v3));
                    *(unsigned*)((bf16*)outv + (size_t)r1 * NC + cn) = *(unsigned*)&o;
                } else {
                    *(float2*)((float*)outv + (size_t)r1 * NC + cn) = make_float2(v2, v3);
                }
            }
        }
    }
}

// ---------------- host orchestration ----------------
extern "C" void kernel_launch(void* const* d_in, const int* in_sizes, int n_in,
                              void* d_out, int out_size) {
    const float* x   = (const float*)d_in[0];
    const int*   ei  = (const int*)d_in[1];
    const int*   src = ei;
    const int*   dst = ei + EE;
    const float* Wc[3] = {(const float*)d_in[2],  (const float*)d_in[8],  (const float*)d_in[14]};
    const float* bc[3] = {(const float*)d_in[3],  (const float*)d_in[9],  (const float*)d_in[15]};
    const float* Wp[3] = {(const float*)d_in[4],  (const float*)d_in[10], (const float*)d_in[16]};
    const float* bp[3] = {(const float*)d_in[5],  (const float*)d_in[11], (const float*)d_in[17]};
    const float* gn[3] = {(const float*)d_in[6],  (const float*)d_in[12], (const float*)d_in[18]};
    const float* be[3] = {(const float*)d_in[7],  (const float*)d_in[13], (const float*)d_in[19]};
    const float* W_in = (const float*)d_in[20];
    const float* b_in = (const float*)d_in[21];
    const float* Wf1  = (const float*)d_in[22];
    const float* bf1  = (const float*)d_in[23];
    const float* Wf2  = (const float*)d_in[24];
    const float* bf2  = (const float*)d_in[25];
    float* outp = (float*)d_out;

    bf16 *p, *sA, *sB, *h, *u, *xb;
    unsigned* wpack;
    float *dv, *csrw;
    int *dg, *rowptr, *cur, *tmp, *bsum, *csrs;
    cudaGetSymbolAddress((void**)&p,  g_p);
    cudaGetSymbolAddress((void**)&sA, g_sA);
    cudaGetSymbolAddress((void**)&sB, g_sB);
    cudaGetSymbolAddress((void**)&h,  g_h);
    cudaGetSymbolAddress((void**)&u,  g_u);
    cudaGetSymbolAddress((void**)&xb, g_xb);
    cudaGetSymbolAddress((void**)&wpack, g_wpack);
    cudaGetSymbolAddress((void**)&dv, g_dinv);
    cudaGetSymbolAddress((void**)&dg, g_deg);
    cudaGetSymbolAddress((void**)&rowptr, g_rowptr);
    cudaGetSymbolAddress((void**)&cur, g_cur);
    cudaGetSymbolAddress((void**)&tmp, g_tmp);
    cudaGetSymbolAddress((void**)&bsum, g_bsum);
    cudaGetSymbolAddress((void**)&csrs, g_csrs);
    cudaGetSymbolAddress((void**)&csrw, g_csrw);

    // ---- pack weights (u32 [K/2][N]) + convert x -> bf16 ----
    unsigned* wc0p = wpack;           unsigned* wc1p = wpack + 16384;
    unsigned* wc2p = wpack + 49152;   unsigned* wp0p = wpack + 81920;
    unsigned* wp1p = wpack + 98304;   unsigned* wp2p = wpack + 131072;
    unsigned* winp = wpack + 163840;  unsigned* wf1p = wpack + 180224;
    unsigned* wf2p = wpack + 245760;
    PackArgs pa;
    pa.seg[0] = {Wc[0], wc0p, 256, 0, 16384};
    pa.seg[1] = {Wc[1], wc1p, 256, 0, 32768};
    pa.seg[2] = {Wc[2], wc2p, 256, 0, 32768};
    pa.seg[3] = {Wp[0], wp0p, 256, 0, 16384};
    pa.seg[4] = {Wp[1], wp1p, 256, 0, 32768};
    pa.seg[5] = {Wp[2], wp2p, 256, 0, 32768};
    pa.seg[6] = {W_in,  winp, 256, 0, 16384};
    pa.seg[7] = {Wf1,   wf1p, 512, 0, 65536};
    pa.seg[8] = {Wf2,   wf2p, 64,  0, 16384};
    pa.seg[9] = {x, (unsigned*)xb, 0, 1, (unsigned)(NN * 64)};
    pa.total = 16384 + 32768 + 32768 + 16384 + 32768 + 32768 + 16384 + 65536 + 16384
             + (unsigned)(NN * 64);
    pack_kernel<<<(pa.total + 255) / 256, 256>>>(pa);

    // ---- CSR build ----
    const int NB = (NN + 1023) / 1024;   // 49
    cudaMemsetAsync(dg, 0, NN * sizeof(int));
    deg_kernel<<<(EE + 255) / 256, 256>>>(dst, dg, EE);
    scan_blk<<<NB, 1024>>>(dg, tmp, bsum, NN);
    scan_top<<<1, 64>>>(bsum, NB);
    scan_add<<<(NN + 1 + 255) / 256, 256>>>(tmp, bsum, dg, dv, rowptr, cur, NN);
    fill_kernel<<<(EE + 255) / 256, 256>>>(src, dst, dv, cur, csrs, csrw, EE);

    // smem sizes
    const int SMEM_CONV = 3 * (128 * 20 + 16 * 264) * 4;   // 81408 B
    const int SMEM128   = 3 * (128 * 20 + 16 * 136) * 4;   // 56832 B
    const int SMEM64    = 3 * (128 * 20 + 16 * 72)  * 4;   // 44544 B
    cudaFuncSetAttribute(conv_gemm_ln<true>,
                         cudaFuncAttributeMaxDynamicSharedMemorySize, SMEM_CONV);
    cudaFuncSetAttribute(conv_gemm_ln<false>,
                         cudaFuncAttributeMaxDynamicSharedMemorySize, SMEM_CONV);
    cudaFuncSetAttribute(bf16_gemm<128, 0, true,  true,  false>,
                         cudaFuncAttributeMaxDynamicSharedMemorySize, SMEM128);
    cudaFuncSetAttribute(bf16_gemm<128, 1, false, true,  false>,
                         cudaFuncAttributeMaxDynamicSharedMemorySize, SMEM128);
    cudaFuncSetAttribute(bf16_gemm<64,  0, false, false, true>,
                         cudaFuncAttributeMaxDynamicSharedMemorySize, SMEM64);

    const int ROWT = (NN + 127) / 128;   // 391
    const dim3 gridConv(1, ROWT);
    const dim3 gridN256(2, ROWT);
    const dim3 gridN512(4, ROWT);
    const dim3 gridN64 (1, ROWT);
    const int gGather = (NN + 7) / 8;

    const unsigned* WcP[3] = {wc0p, wc1p, wc2p};
    const unsigned* WpP[3] = {wp0p, wp1p, wp2p};

    const bf16* hin  = xb;   int din   = 128;
    const bf16* skip = xb;   int dskip = 128;
    bf16* snew_arr[3] = {sA, sB, sA};

    for (int l = 0; l < 3; l++) {
        if (din == 128)
            gather_warp<128><<<gGather, 256>>>(hin, dv, rowptr, csrs, csrw, p);
        else
            gather_warp<256><<<gGather, 256>>>(hin, dv, rowptr, csrs, csrw, p);
        bf16* snew = snew_arr[l];
        if (l < 2) {
            conv_gemm_ln<true><<<gridConv, 512, SMEM_CONV>>>(
                p, WcP[l], din, skip, WpP[l], dskip,
                bc[l], bp[l], gn[l], be[l], snew, h, NN);
        } else {
            conv_gemm_ln<false><<<gridConv, 512, SMEM_CONV>>>(
                p, WcP[l], din, skip, WpP[l], dskip,
                bc[l], bp[l], gn[l], be[l], nullptr, h, NN);
        }
        hin = h; din = 256;
        skip = snew; dskip = 256;
    }

    // t = x @ W_in + b_in + h  -> sA is free?  (sA was layer2's snew target but
    // unwritten for l==2; sB consumed as skip in layer 2) -> use sB
    bf16_gemm<128, 0, true, true, false><<<gridN256, 256, SMEM128>>>(
        xb, winp, 128, b_in, h, sB, NN, 256);
    // u = gelu(t @ Wf1 + bf1)
    bf16_gemm<128, 1, false, true, false><<<gridN512, 256, SMEM128>>>(
        sB, wf1p, 256, bf1, nullptr, u, NN, 512);
    // logits = u @ Wf2 + bf2, fused log_softmax -> d_out (fp32)
    bf16_gemm<64, 0, false, false, true><<<gridN64, 256, SMEM64>>>(
        u, wf2p, 512, bf2, nullptr, outp, NN, 64);
}